// round 10
// baseline (speedup 1.0000x reference)
#include <cuda_runtime.h>
#include <cuda_bf16.h>
#include <cstdint>

// ---------------------------------------------------------------------------
// Problem constants
// ---------------------------------------------------------------------------
#define NROWS 20000
#define KNEI  32
#define CIN   512
#define COUT  512
#define KTOT  1024          // concat [x | mean(neigh)] along features

// GEMM tiling
#define BM 128
#define BN 128
#define BK 32               // 32 bf16 = 64 B per row
#define STAGES 4
#define STAGE_BYTES 16384   // (128*32 + 128*32) * 2B
#define NITH 48             // per half-GEMM: 3 combos * (512/32)
#define NMT 157             // m-tiles
#define NCHUNK 4

// chunk boundaries in m-tiles
__constant__ int c_dummy;   // (unused; keeps nvcc happy about empty constant use)
static const int h_chunk_tiles[NCHUNK + 1] = {0, 40, 80, 120, NMT};

// ---------------------------------------------------------------------------
// Scratch: split bf16 operands (no allocation allowed in kernel_launch).
// ---------------------------------------------------------------------------
__device__ __align__(16) __nv_bfloat16 g_A_hi[(size_t)NROWS * KTOT];
__device__ __align__(16) __nv_bfloat16 g_A_lo[(size_t)NROWS * KTOT];
__device__ __align__(16) __nv_bfloat16 g_B_hi[(size_t)COUT * KTOT];
__device__ __align__(16) __nv_bfloat16 g_B_lo[(size_t)COUT * KTOT];

// ---------------------------------------------------------------------------
// Helpers
// ---------------------------------------------------------------------------
__device__ __forceinline__ uint32_t smem_u32(const void* p) {
    uint32_t a;
    asm("{ .reg .u64 t; cvta.to.shared.u64 t, %1; cvt.u32.u64 %0, t; }"
        : "=r"(a) : "l"(p));
    return a;
}

// Swizzle for 64B rows: 16B-segment index ^= (row>>1)&3.
__device__ __forceinline__ uint32_t swz(uint32_t off) {
    return off ^ ((((off) >> 7) & 3u) << 4);
}

__device__ __forceinline__ void split_bf16(float v, __nv_bfloat16& hi, __nv_bfloat16& lo) {
    hi = __float2bfloat16_rn(v);
    lo = __float2bfloat16_rn(v - __bfloat162float(hi));
}

#define CP_ASYNC_16(dst, src, sz) \
    asm volatile("cp.async.ca.shared.global [%0], [%1], 16, %2;" \
                 :: "r"(dst), "l"(src), "r"(sz))
#define CP_ASYNC_COMMIT() asm volatile("cp.async.commit_group;" ::: "memory")
#define CP_ASYNC_WAIT2()  asm volatile("cp.async.wait_group 2;" ::: "memory")

__device__ __forceinline__ void ldmatrix_x4(uint32_t* r, uint32_t addr) {
    asm volatile("ldmatrix.sync.aligned.m8n8.x4.shared.b16 {%0,%1,%2,%3}, [%4];"
                 : "=r"(r[0]), "=r"(r[1]), "=r"(r[2]), "=r"(r[3]) : "r"(addr));
}
__device__ __forceinline__ void mma_16816(float* c, const uint32_t* a, const uint32_t* b) {
    asm volatile(
        "mma.sync.aligned.m16n8k16.row.col.f32.bf16.bf16.f32 "
        "{%0,%1,%2,%3}, {%4,%5,%6,%7}, {%8,%9}, {%0,%1,%2,%3};"
        : "+f"(c[0]), "+f"(c[1]), "+f"(c[2]), "+f"(c[3])
        : "r"(a[0]), "r"(a[1]), "r"(a[2]), "r"(a[3]), "r"(b[0]), "r"(b[1]));
}

// ---------------------------------------------------------------------------
// Prep: mean over neighbors for rows [r0, r1) -> split -> A[:, 512:1024]
// ---------------------------------------------------------------------------
__global__ void mean_split_kernel(const float* __restrict__ neigh, int r0, int nrows) {
    int idx = blockIdx.x * blockDim.x + threadIdx.x;
    if (idx >= nrows * (CIN / 4)) return;
    int n  = r0 + (idx >> 7);
    int c4 = idx & 127;

    const float4* base = reinterpret_cast<const float4*>(neigh)
                       + (size_t)n * KNEI * (CIN / 4) + c4;
    float4 acc = make_float4(0.f, 0.f, 0.f, 0.f);
#pragma unroll
    for (int k = 0; k < KNEI; k++) {
        float4 v = base[(size_t)k * (CIN / 4)];
        acc.x += v.x; acc.y += v.y; acc.z += v.z; acc.w += v.w;
    }
    const float s = 1.0f / (float)KNEI;
    acc.x *= s; acc.y *= s; acc.z *= s; acc.w *= s;

    __nv_bfloat16 h[4], l[4];
    split_bf16(acc.x, h[0], l[0]);
    split_bf16(acc.y, h[1], l[1]);
    split_bf16(acc.z, h[2], l[2]);
    split_bf16(acc.w, h[3], l[3]);

    size_t off = (size_t)n * KTOT + CIN + c4 * 4;
    __nv_bfloat162* ph = reinterpret_cast<__nv_bfloat162*>(g_A_hi + off);
    __nv_bfloat162* pl = reinterpret_cast<__nv_bfloat162*>(g_A_lo + off);
    ph[0] = __halves2bfloat162(h[0], h[1]);
    ph[1] = __halves2bfloat162(h[2], h[3]);
    pl[0] = __halves2bfloat162(l[0], l[1]);
    pl[1] = __halves2bfloat162(l[2], l[3]);
}

// ---------------------------------------------------------------------------
// Prep: split x -> A[:, 0:512]
// ---------------------------------------------------------------------------
__global__ void x_split_kernel(const float* __restrict__ x) {
    int idx = blockIdx.x * blockDim.x + threadIdx.x;
    if (idx >= NROWS * (CIN / 4)) return;
    int n  = idx >> 7;
    int c4 = idx & 127;

    float4 v = reinterpret_cast<const float4*>(x)[(size_t)n * (CIN / 4) + c4];
    __nv_bfloat16 h[4], l[4];
    split_bf16(v.x, h[0], l[0]);
    split_bf16(v.y, h[1], l[1]);
    split_bf16(v.z, h[2], l[2]);
    split_bf16(v.w, h[3], l[3]);

    size_t off = (size_t)n * KTOT + c4 * 4;
    __nv_bfloat162* ph = reinterpret_cast<__nv_bfloat162*>(g_A_hi + off);
    __nv_bfloat162* pl = reinterpret_cast<__nv_bfloat162*>(g_A_lo + off);
    ph[0] = __halves2bfloat162(h[0], h[1]);
    ph[1] = __halves2bfloat162(h[2], h[3]);
    pl[0] = __halves2bfloat162(l[0], l[1]);
    pl[1] = __halves2bfloat162(l[2], l[3]);
}

// ---------------------------------------------------------------------------
// Prep: split weights -> B (Wl at cols 0:512, Wr at 512:1024)
// ---------------------------------------------------------------------------
__global__ void w_split_kernel(const float* __restrict__ Wl, const float* __restrict__ Wr) {
    int idx = blockIdx.x * blockDim.x + threadIdx.x;
    if (idx >= 2 * COUT * (CIN / 4)) return;
    int sel = idx >= COUT * (CIN / 4);
    int rem = idx - sel * COUT * (CIN / 4);
    int o  = rem >> 7;
    int c4 = rem & 127;

    const float* W = sel ? Wr : Wl;
    float4 v = reinterpret_cast<const float4*>(W)[(size_t)o * (CIN / 4) + c4];
    __nv_bfloat16 h[4], l[4];
    split_bf16(v.x, h[0], l[0]);
    split_bf16(v.y, h[1], l[1]);
    split_bf16(v.z, h[2], l[2]);
    split_bf16(v.w, h[3], l[3]);

    size_t off = (size_t)o * KTOT + sel * CIN + c4 * 4;
    __nv_bfloat162* ph = reinterpret_cast<__nv_bfloat162*>(g_B_hi + off);
    __nv_bfloat162* pl = reinterpret_cast<__nv_bfloat162*>(g_B_lo + off);
    ph[0] = __halves2bfloat162(h[0], h[1]);
    ph[1] = __halves2bfloat162(h[2], h[3]);
    pl[0] = __halves2bfloat162(l[0], l[1]);
    pl[1] = __halves2bfloat162(l[2], l[3]);
}

// ---------------------------------------------------------------------------
// Half-K GEMM: K range [k0, k0+512), m-tiles offset by mtile0.
// ACCUM=0: out = acc + bias.  ACCUM=1: out += acc.
// D = Ahi*Bhi + Ahi*Blo + Alo*Bhi via mma.sync m16n8k16 bf16, fp32 accum.
// ---------------------------------------------------------------------------
__device__ __forceinline__ void load_stage(
    uint32_t sbase, int stage,
    const __nv_bfloat16* __restrict__ A, const __nv_bfloat16* __restrict__ B,
    int bm, int bn, int kcol, int tid)
{
    uint32_t abase = sbase + stage * STAGE_BYTES;
    uint32_t bbase = abase + 8192;
#pragma unroll
    for (int r = 0; r < 4; r++) {
        int s = r * 128 + tid;              // 0..511
        int row = s >> 2, seg = s & 3;
        int gm = bm + row;
        int ok = (gm < NROWS) ? 16 : 0;
        int gmc = (gm < NROWS) ? gm : (NROWS - 1);
        const void* src = A + (size_t)gmc * KTOT + kcol + seg * 8;
        CP_ASYNC_16(abase + swz((uint32_t)(row * 64 + seg * 16)), src, ok);
    }
#pragma unroll
    for (int r = 0; r < 4; r++) {
        int s = r * 128 + tid;
        int row = s >> 2, seg = s & 3;
        const void* src = B + (size_t)(bn + row) * KTOT + kcol + seg * 8;
        CP_ASYNC_16(bbase + swz((uint32_t)(row * 64 + seg * 16)), src, 16);
    }
}

template <int ACCUM>
__global__ __launch_bounds__(128)
void sage_mma_gemm(const __nv_bfloat16* __restrict__ Ahi,
                   const __nv_bfloat16* __restrict__ Alo,
                   const __nv_bfloat16* __restrict__ Bhi,
                   const __nv_bfloat16* __restrict__ Blo,
                   const float* __restrict__ bl,
                   const float* __restrict__ br,
                   float* __restrict__ out,
                   int k0, int mtile0) {
    extern __shared__ __align__(128) char smem[];
    const uint32_t sbase = smem_u32(smem);
    const int tid  = threadIdx.x;
    const int wid  = tid >> 5;
    const int lane = tid & 31;
    const int warp_m = wid & 1;     // 0..1 -> 64-row slab
    const int warp_n = wid >> 1;    // 0..1 -> 64-col slab
    const int bm = (blockIdx.y + mtile0) * BM;
    const int bn = blockIdx.x * BN;

    const __nv_bfloat16* Asel[3] = {Ahi, Ahi, Alo};
    const __nv_bfloat16* Bsel[3] = {Bhi, Blo, Bhi};

    float acc[4][8][4];
#pragma unroll
    for (int i = 0; i < 4; i++)
#pragma unroll
        for (int j = 0; j < 8; j++)
#pragma unroll
            for (int k = 0; k < 4; k++) acc[i][j][k] = 0.f;

    // ldmatrix lane offsets
    const int a_msub = lane & 15;
    const int a_k8   = (lane >> 4) * 8;
    const int b_nsub = (lane & 7) + ((lane >> 4) & 1) * 8;
    const int b_k8   = ((lane >> 3) & 1) * 8;

    // Per-warp precomputed swizzled intra-stage offsets.
    uint32_t a_off[2][4], b_off[2][4];
#pragma unroll
    for (int kk = 0; kk < 2; kk++) {
#pragma unroll
        for (int mi = 0; mi < 4; mi++)
            a_off[kk][mi] = swz((uint32_t)((warp_m * 64 + mi * 16 + a_msub) * 64
                                           + (kk * 16 + a_k8) * 2));
#pragma unroll
        for (int nb = 0; nb < 4; nb++)
            b_off[kk][nb] = swz((uint32_t)((warp_n * 64 + nb * 16 + b_nsub) * 64
                                           + (kk * 16 + b_k8) * 2) + 8192);
    }

    // frag double buffers
    uint32_t afrag[2][4][4];
    uint32_t bfrag[2][4][4];

    // Prologue: fill stages 0..2 (iters 0,1,2 — combos 0,1,2 at kcol=k0)
    load_stage(sbase, 0, Asel[0], Bsel[0], bm, bn, k0, tid);
    CP_ASYNC_COMMIT();
    load_stage(sbase, 1, Asel[1], Bsel[1], bm, bn, k0, tid);
    CP_ASYNC_COMMIT();
    load_stage(sbase, 2, Asel[2], Bsel[2], bm, bn, k0, tid);
    CP_ASYNC_COMMIT();
    CP_ASYNC_WAIT2();            // stage 0 complete
    __syncthreads();

    // preload frags for it=0, kk=0
    {
        uint32_t tb = sbase;
#pragma unroll
        for (int mi = 0; mi < 4; mi++) ldmatrix_x4(afrag[0][mi], tb + a_off[0][mi]);
#pragma unroll
        for (int nb = 0; nb < 4; nb++) ldmatrix_x4(bfrag[0][nb], tb + b_off[0][nb]);
    }

    for (int it = 0; it < NITH; it++) {
        const uint32_t tb = sbase + (uint32_t)(it & 3) * STAGE_BYTES;

        // prefetch kk=1 frags (overlaps with kk=0 MMA burst below)
#pragma unroll
        for (int mi = 0; mi < 4; mi++) ldmatrix_x4(afrag[1][mi], tb + a_off[1][mi]);
#pragma unroll
        for (int nb = 0; nb < 4; nb++) ldmatrix_x4(bfrag[1][nb], tb + b_off[1][nb]);

        // MMA burst kk=0
#pragma unroll
        for (int mi = 0; mi < 4; mi++)
#pragma unroll
            for (int ni = 0; ni < 8; ni++)
                mma_16816(acc[mi][ni], afrag[0][mi], &bfrag[0][ni >> 1][(ni & 1) * 2]);

        // issue load for it+3 into stage (it+3)&3 == (it-1)&3
        if (it + 3 < NITH) {
            int nit = it + 3;
            load_stage(sbase, nit & 3, Asel[nit % 3], Bsel[nit % 3],
                       bm, bn, k0 + (nit / 3) * BK, tid);
        }
        CP_ASYNC_COMMIT();

        // MMA burst kk=1
#pragma unroll
        for (int mi = 0; mi < 4; mi++)
#pragma unroll
            for (int ni = 0; ni < 8; ni++)
                mma_16816(acc[mi][ni], afrag[1][mi], &bfrag[1][ni >> 1][(ni & 1) * 2]);

        CP_ASYNC_WAIT2();        // stage (it+1)&3 load complete
        __syncthreads();         // all warps done reading stage it&3

        // preload next iteration's kk=0 frags
        if (it + 1 < NITH) {
            const uint32_t nb_ = sbase + (uint32_t)((it + 1) & 3) * STAGE_BYTES;
#pragma unroll
            for (int mi = 0; mi < 4; mi++) ldmatrix_x4(afrag[0][mi], nb_ + a_off[0][mi]);
#pragma unroll
            for (int nb = 0; nb < 4; nb++) ldmatrix_x4(bfrag[0][nb], nb_ + b_off[0][nb]);
        }
    }

    // ---- epilogue ----
    const int col0 = bn + warp_n * 64 + (lane & 3) * 2;
    float2 bias[8];
    if (!ACCUM) {
#pragma unroll
        for (int ni = 0; ni < 8; ni++) {
            int c = col0 + ni * 8;
            bias[ni].x = __ldg(bl + c)     + __ldg(br + c);
            bias[ni].y = __ldg(bl + c + 1) + __ldg(br + c + 1);
        }
    }

    const int row0 = bm + warp_m * 64 + (lane >> 2);
#pragma unroll
    for (int mi = 0; mi < 4; mi++) {
#pragma unroll
        for (int h = 0; h < 2; h++) {
            int row = row0 + mi * 16 + h * 8;
            if (row < NROWS) {
                float* orow = out + (size_t)row * COUT;
#pragma unroll
                for (int ni = 0; ni < 8; ni++) {
                    float2 v;
                    if (ACCUM) {
                        float2 old = *reinterpret_cast<const float2*>(orow + col0 + ni * 8);
                        v.x = acc[mi][ni][h * 2 + 0] + old.x;
                        v.y = acc[mi][ni][h * 2 + 1] + old.y;
                    } else {
                        v.x = acc[mi][ni][h * 2 + 0] + bias[ni].x;
                        v.y = acc[mi][ni][h * 2 + 1] + bias[ni].y;
                    }
                    *reinterpret_cast<float2*>(orow + col0 + ni * 8) = v;
                }
            }
        }
    }
}

// ---------------------------------------------------------------------------
// Launch. Chunk-pipelined graph:
//   s0: x_split, w_split, mean_chunk0..3 (event per chunk)
//   s1: after splits: GEMM_x (full), then per chunk: wait -> GEMM_agg(chunk)
//   s0 waits final s1 event.
// ---------------------------------------------------------------------------
extern "C" void kernel_launch(void* const* d_in, const int* in_sizes, int n_in,
                              void* d_out, int out_size) {
    const float* x     = (const float*)d_in[0];
    const float* neigh = (const float*)d_in[1];
    const float* Wl    = (const float*)d_in[2];
    const float* bl    = (const float*)d_in[3];
    const float* Wr    = (const float*)d_in[4];
    const float* br    = (const float*)d_in[5];
    float* out = (float*)d_out;

    __nv_bfloat16 *Ahi, *Alo, *Bhi, *Blo;
    cudaGetSymbolAddress((void**)&Ahi, g_A_hi);
    cudaGetSymbolAddress((void**)&Alo, g_A_lo);
    cudaGetSymbolAddress((void**)&Bhi, g_B_hi);
    cudaGetSymbolAddress((void**)&Blo, g_B_lo);

    // One-time setup (uncaptured correctness call): streams/events/attributes.
    static cudaStream_t s1 = nullptr;
    static cudaEvent_t  e_fork = nullptr, e_done = nullptr;
    static cudaEvent_t  e_mean[NCHUNK];
    if (s1 == nullptr) {
        cudaStreamCreateWithFlags(&s1, cudaStreamNonBlocking);
        cudaEventCreateWithFlags(&e_fork, cudaEventDisableTiming);
        cudaEventCreateWithFlags(&e_done, cudaEventDisableTiming);
        for (int i = 0; i < NCHUNK; i++)
            cudaEventCreateWithFlags(&e_mean[i], cudaEventDisableTiming);
        cudaFuncSetAttribute(sage_mma_gemm<0>,
                             cudaFuncAttributeMaxDynamicSharedMemorySize,
                             STAGES * STAGE_BYTES);
        cudaFuncSetAttribute(sage_mma_gemm<1>,
                             cudaFuncAttributeMaxDynamicSharedMemorySize,
                             STAGES * STAGE_BYTES);
    }

    // ---- s0: x and W splits ----
    {
        int total = NROWS * (CIN / 4);
        x_split_kernel<<<(total + 255) / 256, 256>>>(x);
    }
    {
        int total = 2 * COUT * (CIN / 4);
        w_split_kernel<<<(total + 255) / 256, 256>>>(Wl, Wr);
    }
    cudaEventRecord(e_fork, 0);

    // ---- s0: mean chunks, one event each ----
    for (int c = 0; c < NCHUNK; c++) {
        int r0 = h_chunk_tiles[c] * BM;
        int r1 = (c == NCHUNK - 1) ? NROWS : h_chunk_tiles[c + 1] * BM;
        int nrows = r1 - r0;
        int total = nrows * (CIN / 4);
        mean_split_kernel<<<(total + 255) / 256, 256>>>(neigh, r0, nrows);
        cudaEventRecord(e_mean[c], 0);
    }

    // ---- s1: GEMM_x (depends on splits only), then agg chunks ----
    cudaStreamWaitEvent(s1, e_fork, 0);
    {
        dim3 grid(COUT / BN, NMT);
        sage_mma_gemm<0><<<grid, 128, STAGES * STAGE_BYTES, s1>>>(
            Ahi, Alo, Bhi, Blo, bl, br, out, 0, 0);
    }
    for (int c = 0; c < NCHUNK; c++) {
        cudaStreamWaitEvent(s1, e_mean[c], 0);
        int t0 = h_chunk_tiles[c];
        int nt = h_chunk_tiles[c + 1] - t0;
        dim3 grid(COUT / BN, nt);
        sage_mma_gemm<1><<<grid, 128, STAGES * STAGE_BYTES, s1>>>(
            Ahi, Alo, Bhi, Blo, bl, br, out, CIN, t0);
    }
    cudaEventRecord(e_done, s1);
    cudaStreamWaitEvent(0, e_done, 0);
}

// round 12
// speedup vs baseline: 1.1109x; 1.1109x over previous
#include <cuda_runtime.h>
#include <cuda_bf16.h>
#include <cstdint>

// ---------------------------------------------------------------------------
// Problem constants
// ---------------------------------------------------------------------------
#define NROWS 20000
#define KNEI  32
#define CIN   512
#define COUT  512
#define KTOT  1024          // concat [x | mean(neigh)] along features

// GEMM tiling
#define BM 128
#define BN 128
#define BK 64               // per stage: k64 slab = two 8KB k32 sub-tiles
#define STAGES 3
#define STAGE_BYTES 32768   // [A k0][A k1][B k0][B k1], 8KB each
#define NITH 24             // per half-GEMM: 3 combos * (512/64)
#define NMT 157             // m-tiles

// ---------------------------------------------------------------------------
// Scratch: split bf16 operands (no allocation allowed in kernel_launch).
// ---------------------------------------------------------------------------
__device__ __align__(16) __nv_bfloat16 g_A_hi[(size_t)NROWS * KTOT];
__device__ __align__(16) __nv_bfloat16 g_A_lo[(size_t)NROWS * KTOT];
__device__ __align__(16) __nv_bfloat16 g_B_hi[(size_t)COUT * KTOT];
__device__ __align__(16) __nv_bfloat16 g_B_lo[(size_t)COUT * KTOT];

// ---------------------------------------------------------------------------
// Helpers
// ---------------------------------------------------------------------------
__device__ __forceinline__ uint32_t smem_u32(const void* p) {
    uint32_t a;
    asm("{ .reg .u64 t; cvta.to.shared.u64 t, %1; cvt.u32.u64 %0, t; }"
        : "=r"(a) : "l"(p));
    return a;
}

// Swizzle for 64B rows: 16B-segment index ^= (row>>1)&3.
__device__ __forceinline__ uint32_t swz(uint32_t off) {
    return off ^ ((((off) >> 7) & 3u) << 4);
}

__device__ __forceinline__ void split_bf16(float v, __nv_bfloat16& hi, __nv_bfloat16& lo) {
    hi = __float2bfloat16_rn(v);
    lo = __float2bfloat16_rn(v - __bfloat162float(hi));
}

#define CP_ASYNC_16(dst, src, sz) \
    asm volatile("cp.async.ca.shared.global [%0], [%1], 16, %2;" \
                 :: "r"(dst), "l"(src), "r"(sz))
#define CP_ASYNC_COMMIT() asm volatile("cp.async.commit_group;" ::: "memory")
#define CP_ASYNC_WAIT1()  asm volatile("cp.async.wait_group 1;" ::: "memory")

__device__ __forceinline__ void ldmatrix_x4(uint32_t* r, uint32_t addr) {
    asm volatile("ldmatrix.sync.aligned.m8n8.x4.shared.b16 {%0,%1,%2,%3}, [%4];"
                 : "=r"(r[0]), "=r"(r[1]), "=r"(r[2]), "=r"(r[3]) : "r"(addr));
}
__device__ __forceinline__ void mma_16816(float* c, const uint32_t* a, const uint32_t* b) {
    asm volatile(
        "mma.sync.aligned.m16n8k16.row.col.f32.bf16.bf16.f32 "
        "{%0,%1,%2,%3}, {%4,%5,%6,%7}, {%8,%9}, {%0,%1,%2,%3};"
        : "+f"(c[0]), "+f"(c[1]), "+f"(c[2]), "+f"(c[3])
        : "r"(a[0]), "r"(a[1]), "r"(a[2]), "r"(a[3]), "r"(b[0]), "r"(b[1]));
}

// ---------------------------------------------------------------------------
// Prep: mean over neighbors -> split -> A[:, 512:1024]
// ---------------------------------------------------------------------------
__global__ void mean_split_kernel(const float* __restrict__ neigh) {
    int idx = blockIdx.x * blockDim.x + threadIdx.x;
    if (idx >= NROWS * (CIN / 4)) return;
    int n  = idx >> 7;
    int c4 = idx & 127;

    const float4* base = reinterpret_cast<const float4*>(neigh)
                       + (size_t)n * KNEI * (CIN / 4) + c4;
    float4 acc = make_float4(0.f, 0.f, 0.f, 0.f);
#pragma unroll
    for (int k = 0; k < KNEI; k++) {
        float4 v = base[(size_t)k * (CIN / 4)];
        acc.x += v.x; acc.y += v.y; acc.z += v.z; acc.w += v.w;
    }
    const float s = 1.0f / (float)KNEI;
    acc.x *= s; acc.y *= s; acc.z *= s; acc.w *= s;

    __nv_bfloat16 h[4], l[4];
    split_bf16(acc.x, h[0], l[0]);
    split_bf16(acc.y, h[1], l[1]);
    split_bf16(acc.z, h[2], l[2]);
    split_bf16(acc.w, h[3], l[3]);

    size_t off = (size_t)n * KTOT + CIN + c4 * 4;
    __nv_bfloat162* ph = reinterpret_cast<__nv_bfloat162*>(g_A_hi + off);
    __nv_bfloat162* pl = reinterpret_cast<__nv_bfloat162*>(g_A_lo + off);
    ph[0] = __halves2bfloat162(h[0], h[1]);
    ph[1] = __halves2bfloat162(h[2], h[3]);
    pl[0] = __halves2bfloat162(l[0], l[1]);
    pl[1] = __halves2bfloat162(l[2], l[3]);
}

// ---------------------------------------------------------------------------
// Prep: split x -> A[:, 0:512]
// ---------------------------------------------------------------------------
__global__ void x_split_kernel(const float* __restrict__ x) {
    int idx = blockIdx.x * blockDim.x + threadIdx.x;
    if (idx >= NROWS * (CIN / 4)) return;
    int n  = idx >> 7;
    int c4 = idx & 127;

    float4 v = reinterpret_cast<const float4*>(x)[(size_t)n * (CIN / 4) + c4];
    __nv_bfloat16 h[4], l[4];
    split_bf16(v.x, h[0], l[0]);
    split_bf16(v.y, h[1], l[1]);
    split_bf16(v.z, h[2], l[2]);
    split_bf16(v.w, h[3], l[3]);

    size_t off = (size_t)n * KTOT + c4 * 4;
    __nv_bfloat162* ph = reinterpret_cast<__nv_bfloat162*>(g_A_hi + off);
    __nv_bfloat162* pl = reinterpret_cast<__nv_bfloat162*>(g_A_lo + off);
    ph[0] = __halves2bfloat162(h[0], h[1]);
    ph[1] = __halves2bfloat162(h[2], h[3]);
    pl[0] = __halves2bfloat162(l[0], l[1]);
    pl[1] = __halves2bfloat162(l[2], l[3]);
}

// ---------------------------------------------------------------------------
// Prep: split weights -> B (Wl at cols 0:512, Wr at 512:1024)
// ---------------------------------------------------------------------------
__global__ void w_split_kernel(const float* __restrict__ Wl, const float* __restrict__ Wr) {
    int idx = blockIdx.x * blockDim.x + threadIdx.x;
    if (idx >= 2 * COUT * (CIN / 4)) return;
    int sel = idx >= COUT * (CIN / 4);
    int rem = idx - sel * COUT * (CIN / 4);
    int o  = rem >> 7;
    int c4 = rem & 127;

    const float* W = sel ? Wr : Wl;
    float4 v = reinterpret_cast<const float4*>(W)[(size_t)o * (CIN / 4) + c4];
    __nv_bfloat16 h[4], l[4];
    split_bf16(v.x, h[0], l[0]);
    split_bf16(v.y, h[1], l[1]);
    split_bf16(v.z, h[2], l[2]);
    split_bf16(v.w, h[3], l[3]);

    size_t off = (size_t)o * KTOT + sel * CIN + c4 * 4;
    __nv_bfloat162* ph = reinterpret_cast<__nv_bfloat162*>(g_B_hi + off);
    __nv_bfloat162* pl = reinterpret_cast<__nv_bfloat162*>(g_B_lo + off);
    ph[0] = __halves2bfloat162(h[0], h[1]);
    ph[1] = __halves2bfloat162(h[2], h[3]);
    pl[0] = __halves2bfloat162(l[0], l[1]);
    pl[1] = __halves2bfloat162(l[2], l[3]);
}

// ---------------------------------------------------------------------------
// Half-K GEMM: K range [k0, k0+512).  ACCUM=0: out = acc + bias; 1: out += acc.
// D = Ahi*Bhi + Ahi*Blo + Alo*Bhi via mma.sync m16n8k16 bf16, fp32 accum.
// 128 threads, warp grid 2x2, warp tile 64x64.
// Stage = k64 slab (two k32 sub-tiles); one barrier per 4 kk-steps.
// ---------------------------------------------------------------------------
__device__ __forceinline__ void load_stage(
    uint32_t sbase, int stage,
    const __nv_bfloat16* __restrict__ A, const __nv_bfloat16* __restrict__ B,
    int bm, int bn, int kcol, int tid)
{
    uint32_t base = sbase + stage * STAGE_BYTES;
#pragma unroll
    for (int h = 0; h < 2; h++) {
        uint32_t abase = base + h * 8192;
        uint32_t bbase = base + 16384 + h * 8192;
        int kc = kcol + h * 32;
#pragma unroll
        for (int r = 0; r < 4; r++) {
            int s = r * 128 + tid;              // 0..511
            int row = s >> 2, seg = s & 3;
            int gm = bm + row;
            int ok = (gm < NROWS) ? 16 : 0;
            int gmc = (gm < NROWS) ? gm : (NROWS - 1);
            const void* src = A + (size_t)gmc * KTOT + kc + seg * 8;
            CP_ASYNC_16(abase + swz((uint32_t)(row * 64 + seg * 16)), src, ok);
        }
#pragma unroll
        for (int r = 0; r < 4; r++) {
            int s = r * 128 + tid;
            int row = s >> 2, seg = s & 3;
            const void* src = B + (size_t)(bn + row) * KTOT + kc + seg * 8;
            CP_ASYNC_16(bbase + swz((uint32_t)(row * 64 + seg * 16)), src, 16);
        }
    }
}

template <int ACCUM>
__global__ __launch_bounds__(128)
void sage_mma_gemm(const __nv_bfloat16* __restrict__ Ahi,
                   const __nv_bfloat16* __restrict__ Alo,
                   const __nv_bfloat16* __restrict__ Bhi,
                   const __nv_bfloat16* __restrict__ Blo,
                   const float* __restrict__ bl,
                   const float* __restrict__ br,
                   float* __restrict__ out,
                   int k0) {
    extern __shared__ __align__(128) char smem[];
    const uint32_t sbase = smem_u32(smem);
    const int tid  = threadIdx.x;
    const int wid  = tid >> 5;
    const int lane = tid & 31;
    const int warp_m = wid & 1;     // 0..1 -> 64-row slab
    const int warp_n = wid >> 1;    // 0..1 -> 64-col slab
    const int bm = blockIdx.y * BM;
    const int bn = blockIdx.x * BN;

    const __nv_bfloat16* Asel[3] = {Ahi, Ahi, Alo};
    const __nv_bfloat16* Bsel[3] = {Bhi, Blo, Bhi};

    float acc[4][8][4];
#pragma unroll
    for (int i = 0; i < 4; i++)
#pragma unroll
        for (int j = 0; j < 8; j++)
#pragma unroll
            for (int k = 0; k < 4; k++) acc[i][j][k] = 0.f;

    // ldmatrix lane offsets
    const int a_msub = lane & 15;
    const int a_k8   = (lane >> 4) * 8;
    const int b_nsub = (lane & 7) + ((lane >> 4) & 1) * 8;
    const int b_k8   = ((lane >> 3) & 1) * 8;

    // Intra-sub-tile swizzled offsets for k16 halves 0/1 of an 8KB sub-tile.
    uint32_t a_off[2][4], b_off[2][4];
#pragma unroll
    for (int kk = 0; kk < 2; kk++) {
#pragma unroll
        for (int mi = 0; mi < 4; mi++)
            a_off[kk][mi] = swz((uint32_t)((warp_m * 64 + mi * 16 + a_msub) * 64
                                           + (kk * 16 + a_k8) * 2));
#pragma unroll
        for (int nb = 0; nb < 4; nb++)
            b_off[kk][nb] = swz((uint32_t)((warp_n * 64 + nb * 16 + b_nsub) * 64
                                           + (kk * 16 + b_k8) * 2));
    }

    // frag double buffers (ping-pong across kk steps)
    uint32_t afrag[2][4][4];
    uint32_t bfrag[2][4][4];

    // LDSM of kk-step (0..3) from stage base tb into buffer bf_
#define LOAD_KK(buf, tb, kk) do {                                              \
        uint32_t koffA = ((kk) >> 1) * 8192u;                                  \
        _Pragma("unroll")                                                      \
        for (int mi = 0; mi < 4; mi++)                                         \
            ldmatrix_x4(afrag[buf][mi], (tb) + koffA + a_off[(kk) & 1][mi]);   \
        _Pragma("unroll")                                                      \
        for (int nb = 0; nb < 4; nb++)                                         \
            ldmatrix_x4(bfrag[buf][nb], (tb) + 16384u + koffA + b_off[(kk) & 1][nb]); \
    } while (0)

#define MMA_BURST(buf) do {                                                    \
        _Pragma("unroll")                                                      \
        for (int mi = 0; mi < 4; mi++)                                         \
            _Pragma("unroll")                                                  \
            for (int ni = 0; ni < 8; ni++)                                     \
                mma_16816(acc[mi][ni], afrag[buf][mi],                         \
                          &bfrag[buf][ni >> 1][(ni & 1) * 2]);                 \
    } while (0)

    // Prologue: stages 0 (combo0) and 1 (combo1) at kcol=k0
    load_stage(sbase, 0, Asel[0], Bsel[0], bm, bn, k0, tid);
    CP_ASYNC_COMMIT();
    load_stage(sbase, 1, Asel[1], Bsel[1], bm, bn, k0, tid);
    CP_ASYNC_COMMIT();
    CP_ASYNC_WAIT1();            // stage 0 complete
    __syncthreads();
    LOAD_KK(0, sbase, 0);        // preload it=0 kk=0

    for (int it = 0; it < NITH; it++) {
        const uint32_t tb = sbase + (uint32_t)(it % 3) * STAGE_BYTES;

        LOAD_KK(1, tb, 1);
        MMA_BURST(0);
        LOAD_KK(0, tb, 2);
        MMA_BURST(1);

        // issue load for it+2 into stage (it+2)%3 == (it-1)%3 (readers done)
        if (it + 2 < NITH) {
            int nit = it + 2;
            load_stage(sbase, nit % 3, Asel[nit % 3], Bsel[nit % 3],
                       bm, bn, k0 + (nit / 3) * BK, tid);
        }
        CP_ASYNC_COMMIT();

        LOAD_KK(1, tb, 3);
        MMA_BURST(0);
        MMA_BURST(1);

        CP_ASYNC_WAIT1();        // stage (it+1)%3 load complete
        __syncthreads();         // all warps done reading stage it%3

        if (it + 1 < NITH) {
            const uint32_t ntb = sbase + (uint32_t)((it + 1) % 3) * STAGE_BYTES;
            LOAD_KK(0, ntb, 0);
        }
    }

    // ---- epilogue ----
    const int col0 = bn + warp_n * 64 + (lane & 3) * 2;
    float2 bias[8];
    if (!ACCUM) {
#pragma unroll
        for (int ni = 0; ni < 8; ni++) {
            int c = col0 + ni * 8;
            bias[ni].x = __ldg(bl + c)     + __ldg(br + c);
            bias[ni].y = __ldg(bl + c + 1) + __ldg(br + c + 1);
        }
    }

    const int row0 = bm + warp_m * 64 + (lane >> 2);
#pragma unroll
    for (int mi = 0; mi < 4; mi++) {
#pragma unroll
        for (int h = 0; h < 2; h++) {
            int row = row0 + mi * 16 + h * 8;
            if (row < NROWS) {
                float* orow = out + (size_t)row * COUT;
#pragma unroll
                for (int ni = 0; ni < 8; ni++) {
                    float2 v;
                    if (ACCUM) {
                        float2 old = *reinterpret_cast<const float2*>(orow + col0 + ni * 8);
                        v.x = acc[mi][ni][h * 2 + 0] + old.x;
                        v.y = acc[mi][ni][h * 2 + 1] + old.y;
                    } else {
                        v.x = acc[mi][ni][h * 2 + 0] + bias[ni].x;
                        v.y = acc[mi][ni][h * 2 + 1] + bias[ni].y;
                    }
                    *reinterpret_cast<float2*>(orow + col0 + ni * 8) = v;
                }
            }
        }
    }
#undef LOAD_KK
#undef MMA_BURST
}

// ---------------------------------------------------------------------------
// Launch. Two-stream fork/join (R9 structure):
//   s0: x_split, w_split -> mean_split
//   s1: after splits: GEMM_x (k 0:512, writes out+bias)
//   s0 after mean + GEMM_x: GEMM_agg (k 512:1024, accumulates into out)
// ---------------------------------------------------------------------------
extern "C" void kernel_launch(void* const* d_in, const int* in_sizes, int n_in,
                              void* d_out, int out_size) {
    const float* x     = (const float*)d_in[0];
    const float* neigh = (const float*)d_in[1];
    const float* Wl    = (const float*)d_in[2];
    const float* bl    = (const float*)d_in[3];
    const float* Wr    = (const float*)d_in[4];
    const float* br    = (const float*)d_in[5];
    float* out = (float*)d_out;

    __nv_bfloat16 *Ahi, *Alo, *Bhi, *Blo;
    cudaGetSymbolAddress((void**)&Ahi, g_A_hi);
    cudaGetSymbolAddress((void**)&Alo, g_A_lo);
    cudaGetSymbolAddress((void**)&Bhi, g_B_hi);
    cudaGetSymbolAddress((void**)&Blo, g_B_lo);

    // One-time setup (uncaptured correctness call): stream/events/attributes.
    static cudaStream_t s1 = nullptr;
    static cudaEvent_t  e_fork = nullptr, e_join = nullptr;
    if (s1 == nullptr) {
        cudaStreamCreateWithFlags(&s1, cudaStreamNonBlocking);
        cudaEventCreateWithFlags(&e_fork, cudaEventDisableTiming);
        cudaEventCreateWithFlags(&e_join, cudaEventDisableTiming);
        cudaFuncSetAttribute(sage_mma_gemm<0>,
                             cudaFuncAttributeMaxDynamicSharedMemorySize,
                             STAGES * STAGE_BYTES);
        cudaFuncSetAttribute(sage_mma_gemm<1>,
                             cudaFuncAttributeMaxDynamicSharedMemorySize,
                             STAGES * STAGE_BYTES);
    }

    dim3 grid(COUT / BN, NMT);  // (4, 157)

    // ---- s0: x and W splits ----
    {
        int total = NROWS * (CIN / 4);
        x_split_kernel<<<(total + 255) / 256, 256>>>(x);
    }
    {
        int total = 2 * COUT * (CIN / 4);
        w_split_kernel<<<(total + 255) / 256, 256>>>(Wl, Wr);
    }

    // Fork: GEMM_x on side stream (depends only on x/W splits)
    cudaEventRecord(e_fork, 0);
    cudaStreamWaitEvent(s1, e_fork, 0);
    sage_mma_gemm<0><<<grid, 128, STAGES * STAGE_BYTES, s1>>>(
        Ahi, Alo, Bhi, Blo, bl, br, out, 0);
    cudaEventRecord(e_join, s1);

    // s0 concurrently: mean aggregation + split (HBM-bound)
    {
        int total = NROWS * (CIN / 4);
        mean_split_kernel<<<(total + 255) / 256, 256>>>(neigh);
    }

    // Join, then GEMM_agg accumulates the agg-half into out
    cudaStreamWaitEvent(0, e_join, 0);
    sage_mma_gemm<1><<<grid, 128, STAGES * STAGE_BYTES>>>(
        Ahi, Alo, Bhi, Blo, bl, br, out, CIN);
}